// round 11
// baseline (speedup 1.0000x reference)
#include <cuda_runtime.h>
#include <cuda_bf16.h>
#include <stdint.h>

#define BB 8
#define NN 2048
#define DD 1024
#define NTOK (BB * NN)  // 16384

// ---------------- scratch (allocation-free rule: __device__ globals) --------
__device__ __align__(4096) __nv_bfloat16 g_xh[(size_t)NTOK * DD];
__device__ __align__(4096) __nv_bfloat16 g_xl[(size_t)NTOK * DD];
__device__ __align__(4096) __nv_bfloat16 g_wah[(size_t)DD * DD];
__device__ __align__(4096) __nv_bfloat16 g_wal[(size_t)DD * DD];
__device__ __align__(4096) __nv_bfloat16 g_woh[(size_t)DD * DD];
__device__ __align__(4096) __nv_bfloat16 g_wol[(size_t)DD * DD];
__device__ __align__(4096) __nv_bfloat16 g_kh[(size_t)NTOK * DD];
__device__ __align__(4096) __nv_bfloat16 g_kl[(size_t)NTOK * DD];
__device__ __align__(4096) __nv_bfloat16 g_vth[(size_t)DD * NTOK];  // valT [o][tok]
__device__ __align__(4096) __nv_bfloat16 g_vtl[(size_t)DD * NTOK];
__device__ __align__(4096) __nv_bfloat16 g_ah[(size_t)NTOK * NN];   // attn
__device__ __align__(4096) __nv_bfloat16 g_al[(size_t)NTOK * NN];
__device__ float g_scores[(size_t)BB * NN * NN];                    // 128 MB

// ---------------- PTX helpers ------------------------------------------------
__device__ __forceinline__ uint32_t s2u(const void* p) {
    uint32_t a;
    asm("{ .reg .u64 t; cvta.to.shared.u64 t, %1; cvt.u32.u64 %0, t; }"
        : "=r"(a) : "l"(p));
    return a;
}
__device__ __forceinline__ void cp16(uint32_t dst, const void* src) {
    asm volatile("cp.async.cg.shared.global [%0], [%1], 16;"
                 :: "r"(dst), "l"(src) : "memory");
}
__device__ __forceinline__ void cp_commit() {
    asm volatile("cp.async.commit_group;" ::: "memory");
}
__device__ __forceinline__ void cp_wait1() {
    asm volatile("cp.async.wait_group 1;" ::: "memory");
}
__device__ __forceinline__ void ldsm4(uint32_t* r, uint32_t addr) {
    asm volatile("ldmatrix.sync.aligned.m8n8.x4.shared.b16 {%0,%1,%2,%3}, [%4];"
                 : "=r"(r[0]), "=r"(r[1]), "=r"(r[2]), "=r"(r[3]) : "r"(addr));
}
__device__ __forceinline__ void mma16816(float* c, const uint32_t* a, const uint32_t* b) {
    asm volatile(
        "mma.sync.aligned.m16n8k16.row.col.f32.bf16.bf16.f32 "
        "{%0,%1,%2,%3}, {%4,%5,%6,%7}, {%8,%9}, {%0,%1,%2,%3};"
        : "+f"(c[0]), "+f"(c[1]), "+f"(c[2]), "+f"(c[3])
        : "r"(a[0]), "r"(a[1]), "r"(a[2]), "r"(a[3]), "r"(b[0]), "r"(b[1]));
}

// swizzled smem offset for row r (64B rows), 16B-chunk j
__device__ __forceinline__ uint32_t swz(int r, int j) {
    return (uint32_t)(r * 64 + ((j ^ ((r >> 1) & 3)) << 4));
}

// Stage layout: AH 16K | AL 16K | BH 8K | BL 8K  (A tile 256xk32, B tile 128xk32)
#define STAGE_BYTES 49152
#define SMEM_SZ (3 * STAGE_BYTES)  // 144 KB

// ---------------- bf16x3 NT GEMM body: CTA 256x128, warp 64x64, 1 CTA/SM -----
// C[m,n] = scale * sum_k A[m,k]*B[n,k] (+bias) via AhBh + AhBl + AlBh
// BIAS_MODE: 0 none, 1 bias[n], 2 bias[m].  SPLIT_OUT: write hi/lo bf16.
template <int BIAS_MODE, bool SPLIT_OUT>
__device__ __forceinline__ void gemm_body(
    const __nv_bfloat16* __restrict__ aH, const __nv_bfloat16* __restrict__ aL,
    size_t aStride,
    const __nv_bfloat16* __restrict__ bH, const __nv_bfloat16* __restrict__ bL,
    size_t bStride,
    const float* __restrict__ bias,
    float* __restrict__ C, size_t ldC,
    __nv_bfloat16* __restrict__ oH, __nv_bfloat16* __restrict__ oL, size_t ldO,
    int K, float scale, int m0, int n0, char* smem)
{
    const uint32_t sb = s2u(smem);

    const int t    = threadIdx.x;
    const int lane = t & 31;
    const int wid  = t >> 5;
    const int wm   = wid & 3;     // 0..3 : 64 rows each  (256 total)
    const int wn   = wid >> 2;    // 0..1 : 64 cols each  (128 total)

    const __nv_bfloat16* aHp = aH + (size_t)m0 * aStride;
    const __nv_bfloat16* aLp = aL + (size_t)m0 * aStride;
    const __nv_bfloat16* bHp = bH + (size_t)n0 * bStride;
    const __nv_bfloat16* bLp = bL + (size_t)n0 * bStride;

    const int g    = lane >> 3;
    const int arow = (lane & 7) + ((g & 1) << 3);
    const int ajo  = g >> 1;
    const int brow = (lane & 7) + ((g >> 1) << 3);
    const int bjo  = g & 1;

    float acc[4][8][4] = {};

    // Per stage: A 256 rows x 64 B (1024 chunks/limb), B 128 rows x 64 B (512)
    auto load_stage = [&](int s, int k0) {
        const uint32_t st = sb + (uint32_t)s * STAGE_BYTES;
#pragma unroll
        for (int q = 0; q < 4; q++) {
            const int id = t + 256 * q;
            const int r = id >> 2, j = id & 3;
            const uint32_t dd = swz(r, j);
            cp16(st +         dd, aHp + (size_t)r * aStride + k0 + j * 8);
            cp16(st + 16384 + dd, aLp + (size_t)r * aStride + k0 + j * 8);
        }
#pragma unroll
        for (int q = 0; q < 2; q++) {
            const int id = t + 256 * q;
            const int r = id >> 2, j = id & 3;
            const uint32_t dd = swz(r, j);
            cp16(st + 32768 + dd, bHp + (size_t)r * bStride + k0 + j * 8);
            cp16(st + 40960 + dd, bLp + (size_t)r * bStride + k0 + j * 8);
        }
    };

    load_stage(0, 0);  cp_commit();
    load_stage(1, 32); cp_commit();

    const int iters = K >> 5;
    for (int it = 0; it < iters; it++) {
        cp_wait1();
        __syncthreads();   // stage it%3 ready for all; stage (it-1)%3 consumed

        const uint32_t st = sb + (uint32_t)(it % 3) * STAGE_BYTES;
#pragma unroll
        for (int h = 0; h < 2; h++) {
            uint32_t ah4[4][4], al4[4][4], bh4[4][4], bl4[4][4];
#pragma unroll
            for (int i = 0; i < 4; i++) {
                const int r = wm * 64 + i * 16 + arow;
                const uint32_t off = swz(r, 2 * h + ajo);
                ldsm4(ah4[i], st + off);
                ldsm4(al4[i], st + 16384 + off);
            }
#pragma unroll
            for (int jn = 0; jn < 4; jn++) {
                const int r = wn * 64 + jn * 16 + brow;
                const uint32_t off = swz(r, 2 * h + bjo);
                ldsm4(bh4[jn], st + 32768 + off);
                ldsm4(bl4[jn], st + 40960 + off);
            }
#pragma unroll
            for (int i = 0; i < 4; i++)
#pragma unroll
                for (int j = 0; j < 8; j++)
                    mma16816(acc[i][j], ah4[i], &bh4[j >> 1][(j & 1) * 2]);
#pragma unroll
            for (int i = 0; i < 4; i++)
#pragma unroll
                for (int j = 0; j < 8; j++)
                    mma16816(acc[i][j], ah4[i], &bl4[j >> 1][(j & 1) * 2]);
#pragma unroll
            for (int i = 0; i < 4; i++)
#pragma unroll
                for (int j = 0; j < 8; j++)
                    mma16816(acc[i][j], al4[i], &bh4[j >> 1][(j & 1) * 2]);
        }

        // prefetch stage (it+2): overwrites stage (it-1), proven consumed above
        const int knext = (it + 2) << 5;
        if (knext < K) load_stage((it + 2) % 3, knext);
        cp_commit();
    }

    // ---------------- epilogue ----------------
    const int rin = lane >> 2;
    const int cin = (lane & 3) * 2;
#pragma unroll
    for (int i = 0; i < 4; i++) {
        const int ra = m0 + wm * 64 + i * 16 + rin;
        const int rb = ra + 8;
#pragma unroll
        for (int j = 0; j < 8; j++) {
            const int c = n0 + wn * 64 + j * 8 + cin;
            float v0 = acc[i][j][0] * scale;
            float v1 = acc[i][j][1] * scale;
            float v2 = acc[i][j][2] * scale;
            float v3 = acc[i][j][3] * scale;
            if (BIAS_MODE == 1) {
                const float bc0 = bias[c], bc1 = bias[c + 1];
                v0 += bc0; v1 += bc1; v2 += bc0; v3 += bc1;
            } else if (BIAS_MODE == 2) {
                const float br0 = bias[ra], br1 = bias[rb];
                v0 += br0; v1 += br0; v2 += br1; v3 += br1;
            }
            if (SPLIT_OUT) {
                __nv_bfloat16 h0 = __float2bfloat16(v0), h1 = __float2bfloat16(v1);
                __nv_bfloat16 h2 = __float2bfloat16(v2), h3 = __float2bfloat16(v3);
                __nv_bfloat162 ha; ha.x = h0; ha.y = h1;
                __nv_bfloat162 hb; hb.x = h2; hb.y = h3;
                __nv_bfloat162 la;
                la.x = __float2bfloat16(v0 - __bfloat162float(h0));
                la.y = __float2bfloat16(v1 - __bfloat162float(h1));
                __nv_bfloat162 lb;
                lb.x = __float2bfloat16(v2 - __bfloat162float(h2));
                lb.y = __float2bfloat16(v3 - __bfloat162float(h3));
                *(__nv_bfloat162*)(oH + (size_t)ra * ldO + c) = ha;
                *(__nv_bfloat162*)(oH + (size_t)rb * ldO + c) = hb;
                *(__nv_bfloat162*)(oL + (size_t)ra * ldO + c) = la;
                *(__nv_bfloat162*)(oL + (size_t)rb * ldO + c) = lb;
            } else {
                *(float2*)(C + (size_t)ra * ldC + c) = make_float2(v0, v1);
                *(float2*)(C + (size_t)rb * ldC + c) = make_float2(v2, v3);
            }
        }
    }
}

// ---------------- batched GEMM wrapper (scores / attnV) ----------------------
template <int BIAS_MODE, bool SPLIT_OUT>
__global__ __launch_bounds__(256, 1) void hgemm(
    const __nv_bfloat16* __restrict__ aH, const __nv_bfloat16* __restrict__ aL,
    size_t aStride, size_t aBatch,
    const __nv_bfloat16* __restrict__ bH, const __nv_bfloat16* __restrict__ bL,
    size_t bStride, size_t bBatch,
    const float* __restrict__ bias,
    float* __restrict__ C, size_t ldC, size_t cBatch,
    __nv_bfloat16* __restrict__ oH, __nv_bfloat16* __restrict__ oL, size_t ldO,
    int K, float scale)
{
    extern __shared__ __align__(1024) char smem[];
    const size_t z = blockIdx.z;
    gemm_body<BIAS_MODE, SPLIT_OUT>(
        aH + z * aBatch, aL + z * aBatch, aStride,
        bH + z * bBatch, bL + z * bBatch, bStride,
        bias, C + z * cBatch, ldC, oH, oL, ldO,
        K, scale, blockIdx.y * 256, blockIdx.x * 128, smem);
}

// ---------------- fused projections: key-proj + valT-proj in ONE launch ------
// key tiles: 64 (m) x 8 (n) = 512;  valT tiles: 4 (m) x 128 (n) = 512
__global__ __launch_bounds__(256, 1) void proj_fused(
    const __nv_bfloat16* __restrict__ xh, const __nv_bfloat16* __restrict__ xl,
    const __nv_bfloat16* __restrict__ wah, const __nv_bfloat16* __restrict__ wal,
    const __nv_bfloat16* __restrict__ woh, const __nv_bfloat16* __restrict__ wol,
    const float* __restrict__ b_attn, const float* __restrict__ b_out,
    __nv_bfloat16* __restrict__ kh, __nv_bfloat16* __restrict__ kl,
    __nv_bfloat16* __restrict__ vth, __nv_bfloat16* __restrict__ vtl)
{
    extern __shared__ __align__(1024) char smem[];
    int bid = blockIdx.x;
    if (bid < 512) {
        // key = x @ W_attn^T + b_attn[n]  (M=NTOK, N=DD)
        const int m0 = (bid >> 3) * 256;
        const int n0 = (bid & 7) * 128;
        gemm_body<1, true>(xh, xl, DD, wah, wal, DD, b_attn,
                           nullptr, 0, kh, kl, DD, DD, 1.0f, m0, n0, smem);
    } else {
        // valT = W_out @ x^T + b_out[m]  (M=DD, N=NTOK)
        bid -= 512;
        const int m0 = (bid & 3) * 256;
        const int n0 = (bid >> 2) * 128;
        gemm_body<2, true>(woh, wol, DD, xh, xl, DD, b_out,
                           nullptr, 0, vth, vtl, NTOK, DD, 1.0f, m0, n0, smem);
    }
}

// ---------------- fp32 -> (hi,lo) bf16 converter, row-major -----------------
__global__ __launch_bounds__(256) void convert_split(
    const float* __restrict__ src,
    __nv_bfloat16* __restrict__ dH, __nv_bfloat16* __restrict__ dL)
{
    const size_t i = ((size_t)blockIdx.x * 256 + threadIdx.x) * 8;
    float4 v0 = *(const float4*)(src + i);
    float4 v1 = *(const float4*)(src + i + 4);
    float v[8] = {v0.x, v0.y, v0.z, v0.w, v1.x, v1.y, v1.z, v1.w};
    __align__(16) __nv_bfloat16 h[8], l[8];
#pragma unroll
    for (int e = 0; e < 8; e++) {
        h[e] = __float2bfloat16(v[e]);
        l[e] = __float2bfloat16(v[e] - __bfloat162float(h[e]));
    }
    *(uint4*)(dH + i) = *(const uint4*)h;
    *(uint4*)(dL + i) = *(const uint4*)l;
}

// ---------------- softmax: fp32 scores -> split bf16 attn -------------------
__global__ __launch_bounds__(256) void softmax_split(
    const float* __restrict__ S,
    __nv_bfloat16* __restrict__ aHd, __nv_bfloat16* __restrict__ aLd)
{
    const size_t q = blockIdx.x;
    const float* p = S + q * NN;
    const int t    = threadIdx.x;
    const int lane = t & 31;
    const int wrp  = t >> 5;

    float v[8];
    *(float4*)&v[0] = *(const float4*)&p[t * 8];
    *(float4*)&v[4] = *(const float4*)&p[t * 8 + 4];

    float m = v[0];
#pragma unroll
    for (int i = 1; i < 8; i++) m = fmaxf(m, v[i]);
#pragma unroll
    for (int o = 16; o > 0; o >>= 1) m = fmaxf(m, __shfl_xor_sync(0xffffffffu, m, o));

    __shared__ float red[8];
    if (lane == 0) red[wrp] = m;
    __syncthreads();
    m = red[0];
#pragma unroll
    for (int w = 1; w < 8; w++) m = fmaxf(m, red[w]);
    __syncthreads();

    float s = 0.f;
#pragma unroll
    for (int i = 0; i < 8; i++) { v[i] = __expf(v[i] - m); s += v[i]; }
#pragma unroll
    for (int o = 16; o > 0; o >>= 1) s += __shfl_xor_sync(0xffffffffu, s, o);
    if (lane == 0) red[wrp] = s;
    __syncthreads();
    s = red[0];
#pragma unroll
    for (int w = 1; w < 8; w++) s += red[w];
    const float inv = __frcp_rn(s);

    __align__(16) __nv_bfloat16 h8[8], l8[8];
#pragma unroll
    for (int i = 0; i < 8; i++) {
        float x = v[i] * inv;
        h8[i] = __float2bfloat16(x);
        l8[i] = __float2bfloat16(x - __bfloat162float(h8[i]));
    }
    *(uint4*)(aHd + q * NN + t * 8) = *(const uint4*)h8;
    *(uint4*)(aLd + q * NN + t * 8) = *(const uint4*)l8;
}

// ---------------------------------------------------------------------------
extern "C" void kernel_launch(void* const* d_in, const int* in_sizes, int n_in,
                              void* d_out, int out_size)
{
    const float* x      = (const float*)d_in[0];
    const float* W_attn = (const float*)d_in[1];
    const float* b_attn = (const float*)d_in[2];
    const float* W_out  = (const float*)d_in[3];
    const float* b_out  = (const float*)d_in[4];
    float* out = (float*)d_out;

    __nv_bfloat16 *xh, *xl, *wah, *wal, *woh, *wol, *kh, *kl, *vth, *vtl, *ah, *al;
    float* scores;
    cudaGetSymbolAddress((void**)&xh,  g_xh);  cudaGetSymbolAddress((void**)&xl,  g_xl);
    cudaGetSymbolAddress((void**)&wah, g_wah); cudaGetSymbolAddress((void**)&wal, g_wal);
    cudaGetSymbolAddress((void**)&woh, g_woh); cudaGetSymbolAddress((void**)&wol, g_wol);
    cudaGetSymbolAddress((void**)&kh,  g_kh);  cudaGetSymbolAddress((void**)&kl,  g_kl);
    cudaGetSymbolAddress((void**)&vth, g_vth); cudaGetSymbolAddress((void**)&vtl, g_vtl);
    cudaGetSymbolAddress((void**)&ah,  g_ah);  cudaGetSymbolAddress((void**)&al,  g_al);
    cudaGetSymbolAddress((void**)&scores, g_scores);

    cudaFuncSetAttribute(proj_fused,      cudaFuncAttributeMaxDynamicSharedMemorySize, SMEM_SZ);
    cudaFuncSetAttribute(hgemm<0, false>, cudaFuncAttributeMaxDynamicSharedMemorySize, SMEM_SZ);

    // 0) operand conversion (row-major hi/lo)
    convert_split<<<(NTOK * DD) / 2048, 256>>>(x, xh, xl);
    convert_split<<<(DD * DD) / 2048, 256>>>(W_attn, wah, wal);
    convert_split<<<(DD * DD) / 2048, 256>>>(W_out, woh, wol);

    // 1+2) fused: key = x@W_attn^T + b_attn  AND  valT = W_out@x^T + b_out
    proj_fused<<<1024, 256, SMEM_SZ>>>(xh, xl, wah, wal, woh, wol,
                                       b_attn, b_out, kh, kl, vth, vtl);

    // 3) scores = (x @ key^T) / 32  (batched, fp32 out): 8 (m) x 16 (n) x 8
    hgemm<0, false><<<dim3(NN / 128, NN / 256, BB), 256, SMEM_SZ>>>(
        xh, xl, DD, (size_t)NN * DD, kh, kl, DD, (size_t)NN * DD, nullptr,
        scores, NN, (size_t)NN * NN, nullptr, nullptr, 0, DD, 0.03125f);

    // 4) softmax + split
    softmax_split<<<NTOK, 256>>>(scores, ah, al);

    // 5) out = attn @ valT^T  (batched): 8 (m) x 8 (n) x 8
    hgemm<0, false><<<dim3(DD / 128, NN / 256, BB), 256, SMEM_SZ>>>(
        ah, al, NN, (size_t)NN * NN, vth, vtl, NTOK, (size_t)NN, nullptr,
        out, DD, (size_t)NN * DD, nullptr, nullptr, 0, NN, 1.0f);
}

// round 13
// speedup vs baseline: 1.1394x; 1.1394x over previous
#include <cuda_runtime.h>
#include <cuda_bf16.h>
#include <stdint.h>

#define BB 8
#define NN 2048
#define DD 1024
#define NTOK (BB * NN)  // 16384

// ---------------- scratch (allocation-free rule: __device__ globals) --------
__device__ __align__(4096) __nv_bfloat16 g_xh[(size_t)NTOK * DD];
__device__ __align__(4096) __nv_bfloat16 g_xl[(size_t)NTOK * DD];
__device__ __align__(4096) __nv_bfloat16 g_wah[(size_t)DD * DD];
__device__ __align__(4096) __nv_bfloat16 g_wal[(size_t)DD * DD];
__device__ __align__(4096) __nv_bfloat16 g_woh[(size_t)DD * DD];
__device__ __align__(4096) __nv_bfloat16 g_wol[(size_t)DD * DD];
__device__ __align__(4096) __nv_bfloat16 g_kh[(size_t)NTOK * DD];
__device__ __align__(4096) __nv_bfloat16 g_kl[(size_t)NTOK * DD];
__device__ __align__(4096) __nv_bfloat16 g_vth[(size_t)DD * NTOK];  // valT [o][tok]
__device__ __align__(4096) __nv_bfloat16 g_vtl[(size_t)DD * NTOK];
__device__ __align__(4096) __nv_bfloat16 g_ah[(size_t)NTOK * NN];   // attn
__device__ __align__(4096) __nv_bfloat16 g_al[(size_t)NTOK * NN];
__device__ float g_scores[(size_t)BB * NN * NN];                    // 128 MB

// ---------------- PTX helpers ------------------------------------------------
__device__ __forceinline__ uint32_t s2u(const void* p) {
    uint32_t a;
    asm("{ .reg .u64 t; cvta.to.shared.u64 t, %1; cvt.u32.u64 %0, t; }"
        : "=r"(a) : "l"(p));
    return a;
}
__device__ __forceinline__ void cp16(uint32_t dst, const void* src) {
    asm volatile("cp.async.cg.shared.global [%0], [%1], 16;"
                 :: "r"(dst), "l"(src) : "memory");
}
__device__ __forceinline__ void cp_commit() {
    asm volatile("cp.async.commit_group;" ::: "memory");
}
__device__ __forceinline__ void cp_wait1() {
    asm volatile("cp.async.wait_group 1;" ::: "memory");
}
__device__ __forceinline__ void ldsm4(uint32_t* r, uint32_t addr) {
    asm volatile("ldmatrix.sync.aligned.m8n8.x4.shared.b16 {%0,%1,%2,%3}, [%4];"
                 : "=r"(r[0]), "=r"(r[1]), "=r"(r[2]), "=r"(r[3]) : "r"(addr));
}
__device__ __forceinline__ void mma16816(float* c, const uint32_t* a, const uint32_t* b) {
    asm volatile(
        "mma.sync.aligned.m16n8k16.row.col.f32.bf16.bf16.f32 "
        "{%0,%1,%2,%3}, {%4,%5,%6,%7}, {%8,%9}, {%0,%1,%2,%3};"
        : "+f"(c[0]), "+f"(c[1]), "+f"(c[2]), "+f"(c[3])
        : "r"(a[0]), "r"(a[1]), "r"(a[2]), "r"(a[3]), "r"(b[0]), "r"(b[1]));
}

// swizzled smem offset for row r (64B rows), 16B-chunk j
__device__ __forceinline__ uint32_t swz(int r, int j) {
    return (uint32_t)(r * 64 + ((j ^ ((r >> 1) & 3)) << 4));
}

#define STAGE_BYTES 32768          // AH 8K | AL 8K | BH 8K | BL 8K
#define SMEM_SZ (3 * STAGE_BYTES)  // 96 KB

// ---------------- bf16x3 NT GEMM body (single-sync mainloop) -----------------
// C[m,n] = scale * sum_k A[m,k]*B[n,k] (+bias) via AhBh + AhBl + AlBh
// BIAS_MODE: 0 none, 1 bias[n], 2 bias[m].  SPLIT_OUT: write hi/lo bf16.
template <int BIAS_MODE, bool SPLIT_OUT>
__device__ __forceinline__ void gemm_body(
    const __nv_bfloat16* __restrict__ aH, const __nv_bfloat16* __restrict__ aL,
    size_t aStride,
    const __nv_bfloat16* __restrict__ bH, const __nv_bfloat16* __restrict__ bL,
    size_t bStride,
    const float* __restrict__ bias,
    float* __restrict__ C, size_t ldC,
    __nv_bfloat16* __restrict__ oH, __nv_bfloat16* __restrict__ oL, size_t ldO,
    int K, float scale, int m0, int n0, char* smem)
{
    const uint32_t sb = s2u(smem);

    const int t    = threadIdx.x;
    const int lane = t & 31;
    const int wid  = t >> 5;
    const int wm   = wid >> 2;    // 0..1 : 64 rows each
    const int wn   = wid & 3;     // 0..3 : 32 cols each

    const __nv_bfloat16* aHp = aH + (size_t)m0 * aStride;
    const __nv_bfloat16* aLp = aL + (size_t)m0 * aStride;
    const __nv_bfloat16* bHp = bH + (size_t)n0 * bStride;
    const __nv_bfloat16* bLp = bL + (size_t)n0 * bStride;

    const int r0l = t >> 2,        j0l = t & 3;
    const int r1l = (t >> 2) + 64, j1l = t & 3;
    const uint32_t d0 = swz(r0l, j0l), d1 = swz(r1l, j1l);

    const int g    = lane >> 3;
    const int arow = (lane & 7) + ((g & 1) << 3);
    const int ajo  = g >> 1;
    const int brow = (lane & 7) + ((g >> 1) << 3);
    const int bjo  = g & 1;

    float acc[4][4][4] = {};

    auto load_stage = [&](int s, int k0) {
        const uint32_t st = sb + (uint32_t)s * STAGE_BYTES;
        cp16(st +         d0, aHp + (size_t)r0l * aStride + k0 + j0l * 8);
        cp16(st +         d1, aHp + (size_t)r1l * aStride + k0 + j1l * 8);
        cp16(st +  8192 + d0, aLp + (size_t)r0l * aStride + k0 + j0l * 8);
        cp16(st +  8192 + d1, aLp + (size_t)r1l * aStride + k0 + j1l * 8);
        cp16(st + 16384 + d0, bHp + (size_t)r0l * bStride + k0 + j0l * 8);
        cp16(st + 16384 + d1, bHp + (size_t)r1l * bStride + k0 + j1l * 8);
        cp16(st + 24576 + d0, bLp + (size_t)r0l * bStride + k0 + j0l * 8);
        cp16(st + 24576 + d1, bLp + (size_t)r1l * bStride + k0 + j1l * 8);
    };

    load_stage(0, 0);  cp_commit();
    load_stage(1, 32); cp_commit();

    const int iters = K >> 5;
    for (int it = 0; it < iters; it++) {
        cp_wait1();
        __syncthreads();   // stage it%3 visible to all; stage (it-1)%3 fully consumed

        const uint32_t st = sb + (uint32_t)(it % 3) * STAGE_BYTES;
#pragma unroll
        for (int h = 0; h < 2; h++) {
            uint32_t ah4[4][4], al4[4][4], bh4[2][4], bl4[2][4];
#pragma unroll
            for (int i = 0; i < 4; i++) {
                const int r = wm * 64 + i * 16 + arow;
                const uint32_t off = swz(r, 2 * h + ajo);
                ldsm4(ah4[i], st + off);
                ldsm4(al4[i], st + 8192 + off);
            }
#pragma unroll
            for (int jn = 0; jn < 2; jn++) {
                const int r = wn * 32 + jn * 16 + brow;
                const uint32_t off = swz(r, 2 * h + bjo);
                ldsm4(bh4[jn], st + 16384 + off);
                ldsm4(bl4[jn], st + 24576 + off);
            }
#pragma unroll
            for (int i = 0; i < 4; i++)
#pragma unroll
                for (int j = 0; j < 4; j++)
                    mma16816(acc[i][j], ah4[i], &bh4[j >> 1][(j & 1) * 2]);
#pragma unroll
            for (int i = 0; i < 4; i++)
#pragma unroll
                for (int j = 0; j < 4; j++)
                    mma16816(acc[i][j], ah4[i], &bl4[j >> 1][(j & 1) * 2]);
#pragma unroll
            for (int i = 0; i < 4; i++)
#pragma unroll
                for (int j = 0; j < 4; j++)
                    mma16816(acc[i][j], al4[i], &bh4[j >> 1][(j & 1) * 2]);
        }

        // prefetch stage (it+2): overwrites stage (it-1), proven consumed above
        const int knext = (it + 2) << 5;
        if (knext < K) load_stage((it + 2) % 3, knext);
        cp_commit();
    }

    // ---------------- epilogue ----------------
    const int rin = lane >> 2;
    const int cin = (lane & 3) * 2;
#pragma unroll
    for (int i = 0; i < 4; i++) {
        const int ra = m0 + wm * 64 + i * 16 + rin;
        const int rb = ra + 8;
#pragma unroll
        for (int j = 0; j < 4; j++) {
            const int c = n0 + wn * 32 + j * 8 + cin;
            float v0 = acc[i][j][0] * scale;
            float v1 = acc[i][j][1] * scale;
            float v2 = acc[i][j][2] * scale;
            float v3 = acc[i][j][3] * scale;
            if (BIAS_MODE == 1) {
                const float bc0 = bias[c], bc1 = bias[c + 1];
                v0 += bc0; v1 += bc1; v2 += bc0; v3 += bc1;
            } else if (BIAS_MODE == 2) {
                const float br0 = bias[ra], br1 = bias[rb];
                v0 += br0; v1 += br0; v2 += br1; v3 += br1;
            }
            if (SPLIT_OUT) {
                __nv_bfloat16 h0 = __float2bfloat16(v0), h1 = __float2bfloat16(v1);
                __nv_bfloat16 h2 = __float2bfloat16(v2), h3 = __float2bfloat16(v3);
                __nv_bfloat162 ha; ha.x = h0; ha.y = h1;
                __nv_bfloat162 hb; hb.x = h2; hb.y = h3;
                __nv_bfloat162 la;
                la.x = __float2bfloat16(v0 - __bfloat162float(h0));
                la.y = __float2bfloat16(v1 - __bfloat162float(h1));
                __nv_bfloat162 lb;
                lb.x = __float2bfloat16(v2 - __bfloat162float(h2));
                lb.y = __float2bfloat16(v3 - __bfloat162float(h3));
                *(__nv_bfloat162*)(oH + (size_t)ra * ldO + c) = ha;
                *(__nv_bfloat162*)(oH + (size_t)rb * ldO + c) = hb;
                *(__nv_bfloat162*)(oL + (size_t)ra * ldO + c) = la;
                *(__nv_bfloat162*)(oL + (size_t)rb * ldO + c) = lb;
            } else {
                *(float2*)(C + (size_t)ra * ldC + c) = make_float2(v0, v1);
                *(float2*)(C + (size_t)rb * ldC + c) = make_float2(v2, v3);
            }
        }
    }
}

// ---------------- batched GEMM wrapper (scores / attnV) ----------------------
template <int BIAS_MODE, bool SPLIT_OUT>
__global__ __launch_bounds__(256, 2) void hgemm(
    const __nv_bfloat16* __restrict__ aH, const __nv_bfloat16* __restrict__ aL,
    size_t aStride, size_t aBatch,
    const __nv_bfloat16* __restrict__ bH, const __nv_bfloat16* __restrict__ bL,
    size_t bStride, size_t bBatch,
    const float* __restrict__ bias,
    float* __restrict__ C, size_t ldC, size_t cBatch,
    __nv_bfloat16* __restrict__ oH, __nv_bfloat16* __restrict__ oL, size_t ldO,
    int K, float scale)
{
    extern __shared__ __align__(1024) char smem[];
    const size_t z = blockIdx.z;
    gemm_body<BIAS_MODE, SPLIT_OUT>(
        aH + z * aBatch, aL + z * aBatch, aStride,
        bH + z * bBatch, bL + z * bBatch, bStride,
        bias, C + z * cBatch, ldC, oH, oL, ldO,
        K, scale, blockIdx.y * 128, blockIdx.x * 128, smem);
}

// ---------------- fused projections: key-proj + valT-proj in ONE launch ------
__global__ __launch_bounds__(256, 2) void proj_fused(
    const __nv_bfloat16* __restrict__ xh, const __nv_bfloat16* __restrict__ xl,
    const __nv_bfloat16* __restrict__ wah, const __nv_bfloat16* __restrict__ wal,
    const __nv_bfloat16* __restrict__ woh, const __nv_bfloat16* __restrict__ wol,
    const float* __restrict__ b_attn, const float* __restrict__ b_out,
    __nv_bfloat16* __restrict__ kh, __nv_bfloat16* __restrict__ kl,
    __nv_bfloat16* __restrict__ vth, __nv_bfloat16* __restrict__ vtl)
{
    extern __shared__ __align__(1024) char smem[];
    int bid = blockIdx.x;
    if (bid < 1024) {
        // key = x @ W_attn^T + b_attn[n]  (M=NTOK, N=DD)
        const int m0 = (bid >> 3) * 128;
        const int n0 = (bid & 7) * 128;
        gemm_body<1, true>(xh, xl, DD, wah, wal, DD, b_attn,
                           nullptr, 0, kh, kl, DD, DD, 1.0f, m0, n0, smem);
    } else {
        // valT = W_out @ x^T + b_out[m]  (M=DD, N=NTOK)
        bid -= 1024;
        const int m0 = (bid & 7) * 128;
        const int n0 = (bid >> 3) * 128;
        gemm_body<2, true>(woh, wol, DD, xh, xl, DD, b_out,
                           nullptr, 0, vth, vtl, NTOK, DD, 1.0f, m0, n0, smem);
    }
}

// ---------------- fused fp32 -> (hi,lo) bf16 converter (x, W_attn, W_out) ----
// blocks 0..8191 -> x; 8192..8703 -> W_attn; 8704..9215 -> W_out
__global__ __launch_bounds__(256) void convert_all(
    const float* __restrict__ x, const float* __restrict__ wa,
    const float* __restrict__ wo,
    __nv_bfloat16* __restrict__ xh, __nv_bfloat16* __restrict__ xl,
    __nv_bfloat16* __restrict__ wah, __nv_bfloat16* __restrict__ wal,
    __nv_bfloat16* __restrict__ woh, __nv_bfloat16* __restrict__ wol)
{
    const int b = blockIdx.x;
    const float* src;
    __nv_bfloat16 *dH, *dL;
    size_t base;
    if (b < 8192)       { src = x;  dH = xh;  dL = xl;  base = (size_t)b * 2048; }
    else if (b < 8704)  { src = wa; dH = wah; dL = wal; base = (size_t)(b - 8192) * 2048; }
    else                { src = wo; dH = woh; dL = wol; base = (size_t)(b - 8704) * 2048; }

    const size_t i = base + (size_t)threadIdx.x * 8;
    float4 v0 = *(const float4*)(src + i);
    float4 v1 = *(const float4*)(src + i + 4);
    float v[8] = {v0.x, v0.y, v0.z, v0.w, v1.x, v1.y, v1.z, v1.w};
    __align__(16) __nv_bfloat16 h[8], l[8];
#pragma unroll
    for (int e = 0; e < 8; e++) {
        h[e] = __float2bfloat16(v[e]);
        l[e] = __float2bfloat16(v[e] - __bfloat162float(h[e]));
    }
    *(uint4*)(dH + i) = *(const uint4*)h;
    *(uint4*)(dL + i) = *(const uint4*)l;
}

// ---------------- softmax: fp32 scores -> split bf16 attn -------------------
__global__ __launch_bounds__(256) void softmax_split(
    const float* __restrict__ S,
    __nv_bfloat16* __restrict__ aHd, __nv_bfloat16* __restrict__ aLd)
{
    const size_t q = blockIdx.x;
    const float* p = S + q * NN;
    const int t    = threadIdx.x;
    const int lane = t & 31;
    const int wrp  = t >> 5;

    float v[8];
    *(float4*)&v[0] = *(const float4*)&p[t * 8];
    *(float4*)&v[4] = *(const float4*)&p[t * 8 + 4];

    float m = v[0];
#pragma unroll
    for (int i = 1; i < 8; i++) m = fmaxf(m, v[i]);
#pragma unroll
    for (int o = 16; o > 0; o >>= 1) m = fmaxf(m, __shfl_xor_sync(0xffffffffu, m, o));

    __shared__ float red[8];
    if (lane == 0) red[wrp] = m;
    __syncthreads();
    m = red[0];
#pragma unroll
    for (int w = 1; w < 8; w++) m = fmaxf(m, red[w]);
    __syncthreads();

    float s = 0.f;
#pragma unroll
    for (int i = 0; i < 8; i++) { v[i] = __expf(v[i] - m); s += v[i]; }
#pragma unroll
    for (int o = 16; o > 0; o >>= 1) s += __shfl_xor_sync(0xffffffffu, s, o);
    if (lane == 0) red[wrp] = s;
    __syncthreads();
    s = red[0];
#pragma unroll
    for (int w = 1; w < 8; w++) s += red[w];
    const float inv = __frcp_rn(s);

    __align__(16) __nv_bfloat16 h8[8], l8[8];
#pragma unroll
    for (int i = 0; i < 8; i++) {
        float x = v[i] * inv;
        h8[i] = __float2bfloat16(x);
        l8[i] = __float2bfloat16(x - __bfloat162float(h8[i]));
    }
    *(uint4*)(aHd + q * NN + t * 8) = *(const uint4*)h8;
    *(uint4*)(aLd + q * NN + t * 8) = *(const uint4*)l8;
}

// ---------------------------------------------------------------------------
extern "C" void kernel_launch(void* const* d_in, const int* in_sizes, int n_in,
                              void* d_out, int out_size)
{
    const float* x      = (const float*)d_in[0];
    const float* W_attn = (const float*)d_in[1];
    const float* b_attn = (const float*)d_in[2];
    const float* W_out  = (const float*)d_in[3];
    const float* b_out  = (const float*)d_in[4];
    float* out = (float*)d_out;

    __nv_bfloat16 *xh, *xl, *wah, *wal, *woh, *wol, *kh, *kl, *vth, *vtl, *ah, *al;
    float* scores;
    cudaGetSymbolAddress((void**)&xh,  g_xh);  cudaGetSymbolAddress((void**)&xl,  g_xl);
    cudaGetSymbolAddress((void**)&wah, g_wah); cudaGetSymbolAddress((void**)&wal, g_wal);
    cudaGetSymbolAddress((void**)&woh, g_woh); cudaGetSymbolAddress((void**)&wol, g_wol);
    cudaGetSymbolAddress((void**)&kh,  g_kh);  cudaGetSymbolAddress((void**)&kl,  g_kl);
    cudaGetSymbolAddress((void**)&vth, g_vth); cudaGetSymbolAddress((void**)&vtl, g_vtl);
    cudaGetSymbolAddress((void**)&ah,  g_ah);  cudaGetSymbolAddress((void**)&al,  g_al);
    cudaGetSymbolAddress((void**)&scores, g_scores);

    cudaFuncSetAttribute(proj_fused,      cudaFuncAttributeMaxDynamicSharedMemorySize, SMEM_SZ);
    cudaFuncSetAttribute(hgemm<0, false>, cudaFuncAttributeMaxDynamicSharedMemorySize, SMEM_SZ);

    // 0) operand conversion (x + both weights, one launch)
    convert_all<<<9216, 256>>>(x, W_attn, W_out, xh, xl, wah, wal, woh, wol);

    // 1+2) fused: key = x@W_attn^T + b_attn  AND  valT = W_out@x^T + b_out
    proj_fused<<<2048, 256, SMEM_SZ>>>(xh, xl, wah, wal, woh, wol,
                                       b_attn, b_out, kh, kl, vth, vtl);

    // 3) scores = (x @ key^T) / 32  (batched, fp32 out)
    hgemm<0, false><<<dim3(NN / 128, NN / 128, BB), 256, SMEM_SZ>>>(
        xh, xl, DD, (size_t)NN * DD, kh, kl, DD, (size_t)NN * DD, nullptr,
        scores, NN, (size_t)NN * NN, nullptr, nullptr, 0, DD, 0.03125f);

    // 4) softmax + split
    softmax_split<<<NTOK, 256>>>(scores, ah, al);

    // 5) out = attn @ valT^T  (batched, fp32 out; batches via column offset)
    hgemm<0, false><<<dim3(DD / 128, NN / 128, BB), 256, SMEM_SZ>>>(
        ah, al, NN, (size_t)NN * NN, vth, vtl, NTOK, (size_t)NN, nullptr,
        out, DD, (size_t)NN * DD, nullptr, nullptr, 0, NN, 1.0f);
}